// round 11
// baseline (speedup 1.0000x reference)
#include <cuda_runtime.h>
#include <cuda_fp16.h>
#include <cstdint>

#define DEPTH 4
#define B_    4096
#define H_    1024
#define K_    2048
#define N4H   4096

// ---------------- device scratch ----------------
__device__ __half g_A[DEPTH][B_][K_];    // [prev_out | s_h] fp16
__device__ __half g_W[DEPTH][K_][N4H];   // gate-interleaved: col 4j+g = orig g*1024+j
__device__ int    g_ticket;
__device__ int    g_ready[DEPTH][32];    // finished n-tiles per (layer, m-block)
__device__ int    g_wready[DEPTH];       // W conversion chunks done (32 = full)
__device__ int    g_xready;              // x pack chunks done (16 = full)
__device__ int    g_shready[DEPTH];      // s_h pack chunks done (16 = full)

// ---------------- helpers ----------------
__device__ __forceinline__ uint32_t smem_u32(const void* p) {
    uint32_t a;
    asm("{ .reg .u64 t; cvta.to.shared.u64 t, %1; cvt.u32.u64 %0, t; }" : "=r"(a) : "l"(p));
    return a;
}
__device__ __forceinline__ void cp16(uint32_t dst, const void* src) {
    asm volatile("cp.async.cg.shared.global [%0], [%1], 16;"
                 :: "r"(dst), "l"(__cvta_generic_to_global(src)));
}
__device__ __forceinline__ void ldsm4(uint32_t* r, uint32_t addr) {
    asm volatile("ldmatrix.sync.aligned.m8n8.x4.shared.b16 {%0,%1,%2,%3}, [%4];"
                 : "=r"(r[0]), "=r"(r[1]), "=r"(r[2]), "=r"(r[3]) : "r"(addr));
}
__device__ __forceinline__ void ldsm4t(uint32_t* r, uint32_t addr) {
    asm volatile("ldmatrix.sync.aligned.m8n8.x4.trans.shared.b16 {%0,%1,%2,%3}, [%4];"
                 : "=r"(r[0]), "=r"(r[1]), "=r"(r[2]), "=r"(r[3]) : "r"(addr));
}
__device__ __forceinline__ void mma16816(float* c, const uint32_t* a, const uint32_t* b) {
    asm volatile("mma.sync.aligned.m16n8k16.row.col.f32.f16.f16.f32 "
                 "{%0,%1,%2,%3}, {%4,%5,%6,%7}, {%8,%9}, {%0,%1,%2,%3};"
                 : "+f"(c[0]), "+f"(c[1]), "+f"(c[2]), "+f"(c[3])
                 : "r"(a[0]), "r"(a[1]), "r"(a[2]), "r"(a[3]), "r"(b[0]), "r"(b[1]));
}
__device__ __forceinline__ float sigm(float x) { return 1.0f / (1.0f + __expf(-x)); }

__device__ __forceinline__ void wait_ge(const int* cp, int thr) {
    int v;
    for (;;) {
        asm volatile("ld.global.acquire.gpu.b32 %0, [%1];" : "=r"(v) : "l"(cp) : "memory");
        if (v >= thr) break;
        __nanosleep(128);
    }
}

// ---------------- init ----------------
__global__ void init_counters() {
    int t = threadIdx.x;
    if (t == 0) { g_ticket = 0; g_xready = 0; }
    if (t < DEPTH * 32) ((int*)g_ready)[t] = 0;
    if (t < DEPTH) { g_wready[t] = 0; g_shready[t] = 0; }
}

// ---------------- tile config ----------------
#define BK      32
#define ASTRIDE 80
#define BSTRIDE 272
#define A_STG   (128 * ASTRIDE)    // 10240
#define B_STG   (BK * BSTRIDE)     // 8704
#define STG     (A_STG + B_STG)    // 18944
#define NSTAGE  5
#define CIN_STRIDE 144
#define CIN_BYTES  (128 * CIN_STRIDE)
#define SMEM_G  (NSTAGE * STG + CIN_BYTES)     // 113152
#define NCONV   208
#define NTILES  (DEPTH * 32 * 32)              // 4096
#define NTOT    (NCONV + NTILES)
#define GRID_P  296

// ---------------- conversion chunks (phase 0) ----------------
// W'[l][k][4j+g] = W[l][k][g*1024+j]  (mapping verified: rel_err identical)
__device__ void conv_w(int l, int c, const float* __restrict__ W) {
    const int k0 = c * 64;
    const int tid = threadIdx.x;
    #pragma unroll 4
    for (int it = 0; it < 256; ++it) {
        int idx = tid + 256 * it;          // 64 k-rows x 1024 j
        int k = k0 + (idx >> 10), j = idx & 1023;
        const float* src = W + ((size_t)l * K_ + k) * N4H;
        float vi = src[j], vf = src[1024 + j], vo = src[2048 + j], vg = src[3072 + j];
        __half2* dst = (__half2*)&g_W[l][k][4 * j];
        dst[0] = __floats2half2_rn(vi, vf);
        dst[1] = __floats2half2_rn(vo, vg);
    }
}
__device__ void conv_x(int c, const float* __restrict__ x) {
    const int m0 = c * 256;
    const int tid = threadIdx.x;
    #pragma unroll 4
    for (int it = 0; it < 256; ++it) {
        int idx = tid + 256 * it;          // 256 rows x 256 float4
        int m = m0 + (idx >> 8), j = (idx & 255) * 4;
        float4 v = *(const float4*)&x[(size_t)m * H_ + j];
        __half2* dst = (__half2*)&g_A[0][m][j];
        dst[0] = __floats2half2_rn(v.x, v.y);
        dst[1] = __floats2half2_rn(v.z, v.w);
    }
}
__device__ void conv_sh(int l, int c, const float* __restrict__ sh) {
    const int m0 = c * 256;
    const int tid = threadIdx.x;
    const float* src = sh + (size_t)l * B_ * H_;
    #pragma unroll 4
    for (int it = 0; it < 256; ++it) {
        int idx = tid + 256 * it;
        int m = m0 + (idx >> 8), j = (idx & 255) * 4;
        float4 v = *(const float4*)&src[(size_t)m * H_ + j];
        __half2* dst = (__half2*)&g_A[l][m][H_ + j];
        dst[0] = __floats2half2_rn(v.x, v.y);
        dst[1] = __floats2half2_rn(v.z, v.w);
    }
}

// ---------------- GEMM + LSTM tile (R9-verified) ----------------
__device__ __forceinline__ void process_tile(
    int layer, int m0, int n0, char* smem,
    const float* __restrict__ bias_all, const float* __restrict__ sc_all,
    float* __restrict__ out_h, float* __restrict__ out_c,
    float* __restrict__ out_final)
{
    const uint32_t sbase = smem_u32(smem);
    const uint32_t scin  = sbase + NSTAGE * STG;

    const int tid = threadIdx.x;
    const int wid = tid >> 5, lane = tid & 31;
    const int jbase = n0 >> 2;
    const int wm = (wid >> 2) * 64, wn = (wid & 3) * 32;

    const float* bias = bias_all + (size_t)layer * N4H;
    const float* c_in = sc_all + (size_t)layer * B_ * H_;
    float* h_out = out_h + (size_t)layer * B_ * H_;
    float* c_out = out_c + (size_t)layer * B_ * H_;
    float* final_out = (layer == DEPTH - 1) ? out_final : nullptr;

    const __half* Ag = &g_A[layer][0][0];
    const __half* Wg = &g_W[layer][0][0];
    __half* a_next = (layer + 1 < DEPTH) ? &g_A[layer + 1][0][0] : nullptr;

    const int ar = tid >> 1, ac = (tid & 1) * 2;
    const int br = tid >> 4, bc = tid & 15;

    auto load_stage = [&](int s, int k0) {
        uint32_t da = sbase + s * STG;
        uint32_t db = da + A_STG;
        cp16(da + ar * ASTRIDE + ac * 16,       Ag + (size_t)(m0 + ar) * K_ + k0 + ac * 8);
        cp16(da + ar * ASTRIDE + (ac + 1) * 16, Ag + (size_t)(m0 + ar) * K_ + k0 + (ac + 1) * 8);
        cp16(db + br * BSTRIDE + bc * 16,        Wg + (size_t)(k0 + br) * N4H + n0 + bc * 8);
        cp16(db + (br + 16) * BSTRIDE + bc * 16, Wg + (size_t)(k0 + br + 16) * N4H + n0 + bc * 8);
        asm volatile("cp.async.commit_group;" ::: "memory");
    };

    float acc[4][4][4];
    #pragma unroll
    for (int i = 0; i < 4; ++i)
        #pragma unroll
        for (int j = 0; j < 4; ++j)
            #pragma unroll
            for (int q = 0; q < 4; ++q) acc[i][j][q] = 0.f;

    #pragma unroll
    for (int it = 0; it < 4; ++it) {
        int idx = tid + 256 * it;
        int r = idx >> 3, ch = idx & 7;
        cp16(scin + r * CIN_STRIDE + ch * 16,
             c_in + (size_t)(m0 + r) * H_ + jbase + ch * 4);
    }
    asm volatile("cp.async.commit_group;" ::: "memory");

    load_stage(0, 0);
    load_stage(1, BK);
    load_stage(2, 2 * BK);

    uint32_t aoff[4], boff[2];
    #pragma unroll
    for (int mf = 0; mf < 4; ++mf)
        aoff[mf] = (wm + mf * 16 + (lane & 15)) * ASTRIDE + (lane >> 4) * 16;
    #pragma unroll
    for (int ns = 0; ns < 2; ++ns)
        boff[ns] = (lane & 15) * BSTRIDE + (wn + ns * 16 + (lane >> 4) * 8) * 2;

    auto subiter = [&](int st, int pf_slot, int pf_k0, bool do_pf) {
        const uint32_t da = sbase + st * STG;
        const uint32_t db = da + A_STG;
        uint32_t af[4][4], bf[2][4];
        #pragma unroll
        for (int mf = 0; mf < 4; ++mf) ldsm4(af[mf], da + aoff[mf]);
        #pragma unroll
        for (int ns = 0; ns < 2; ++ns) ldsm4t(bf[ns], db + boff[ns]);
        if (do_pf) load_stage(pf_slot, pf_k0);
        #pragma unroll
        for (int mf = 0; mf < 4; ++mf)
            #pragma unroll
            for (int nf = 0; nf < 4; ++nf)
                mma16816(acc[mf][nf], af[mf], &bf[nf >> 1][(nf & 1) * 2]);
        #pragma unroll
        for (int mf = 0; mf < 4; ++mf) ldsm4(af[mf], da + aoff[mf] + 32);
        #pragma unroll
        for (int ns = 0; ns < 2; ++ns) ldsm4t(bf[ns], db + boff[ns] + 16 * BSTRIDE);
        #pragma unroll
        for (int mf = 0; mf < 4; ++mf)
            #pragma unroll
            for (int nf = 0; nf < 4; ++nf)
                mma16816(acc[mf][nf], af[mf], &bf[nf >> 1][(nf & 1) * 2]);
    };

    const int NIT = K_ / BK;  // 64
    #pragma unroll 1
    for (int kt = 0; kt < NIT; kt += 2) {
        if (kt + 2 < NIT) asm volatile("cp.async.wait_group 1;" ::: "memory");
        else              asm volatile("cp.async.wait_group 0;" ::: "memory");
        __syncthreads();
        subiter(kt % NSTAGE,       (kt + 3) % NSTAGE, (kt + 3) * BK, kt + 3 < NIT);
        subiter((kt + 1) % NSTAGE, (kt + 4) % NSTAGE, (kt + 4) * BK, kt + 4 < NIT);
    }
    __syncthreads();

    float* sh_h = (float*)smem;                     // [128][33]
    float* sh_c = sh_h + 128 * 33;                  // [128][33]
    const float* sh_cin = (const float*)(smem + (NSTAGE * STG));

    const int q = lane & 3;
    const bool has_if = (q & 1) == 0;
    const int rloc = wm + (lane >> 2);

    float bi[4], bfs[4], bo[4], bg[4];
    int jloc[4];
    #pragma unroll
    for (int nf = 0; nf < 4; ++nf) {
        int jl = (wn >> 2) + nf * 2 + (q >> 1);
        jloc[nf] = jl;
        int j = jbase + jl;
        bi[nf]  = bias[j];
        bfs[nf] = bias[1024 + j];
        bo[nf]  = bias[2048 + j];
        bg[nf]  = bias[3072 + j];
    }

    #pragma unroll
    for (int mf = 0; mf < 4; ++mf) {
        #pragma unroll
        for (int nf = 0; nf < 4; ++nf) {
            float v0 = acc[mf][nf][0], v1 = acc[mf][nf][1];
            float v2 = acc[mf][nf][2], v3 = acc[mf][nf][3];
            float p0 = __shfl_xor_sync(0xffffffffu, v0, 1);
            float p1 = __shfl_xor_sync(0xffffffffu, v1, 1);
            float p2 = __shfl_xor_sync(0xffffffffu, v2, 1);
            float p3 = __shfl_xor_sync(0xffffffffu, v3, 1);
            float zi, zf, zo, zg;
            int ml;
            if (has_if) { zi = v0; zf = v1; zo = p0; zg = p1; ml = rloc + mf * 16; }
            else        { zi = p2; zf = p3; zo = v2; zg = v3; ml = rloc + mf * 16 + 8; }
            const int jl = jloc[nf];
            float ig = sigm(zi + bi[nf]);
            float fg = sigm(zf + bfs[nf]);
            float og = sigm(zo + bo[nf]);
            float gg = tanhf(zg + bg[nf]);
            float cn = sh_cin[ml * 36 + jl] * fg + gg * ig;
            float hn = tanhf(cn) * og;
            sh_h[ml * 33 + jl] = hn;
            sh_c[ml * 33 + jl] = cn;
        }
    }
    __syncthreads();

    #pragma unroll
    for (int it = 0; it < 16; ++it) {
        int idx = tid + 256 * it;
        int r = idx >> 5, c2 = idx & 31;
        float hv = sh_h[r * 33 + c2];
        float cv = sh_c[r * 33 + c2];
        const size_t off = (size_t)(m0 + r) * H_ + jbase + c2;
        h_out[off] = hv;
        c_out[off] = cv;
        if (final_out) final_out[off] = hv;
        if (a_next) a_next[(size_t)(m0 + r) * K_ + jbase + c2] = __float2half(hv);
    }
    __syncthreads();
}

// ---------------- persistent kernel: conversion phase + GEMM phase ----------------
__global__ void __launch_bounds__(256, 2)
lstm_all(const float* __restrict__ x, const float* __restrict__ sh,
         const float* __restrict__ W,
         const float* __restrict__ bias_all, const float* __restrict__ sc_all,
         float* __restrict__ out_h, float* __restrict__ out_c,
         float* __restrict__ out_final) {
    extern __shared__ __align__(16) char smem[];
    __shared__ int s_t;
    const int tid = threadIdx.x;

    for (;;) {
        if (tid == 0) s_t = atomicAdd(&g_ticket, 1);
        __syncthreads();
        const int t = s_t;
        if (t >= NTOT) return;

        if (t < NCONV) {
            // phase 0: conversion tickets, ordered so layer-0 inputs finish first
            int* ctr;
            if      (t < 32)  { conv_w(0, t, W);          ctr = &g_wready[0]; }
            else if (t < 48)  { conv_x(t - 32, x);        ctr = &g_xready;    }
            else if (t < 64)  { conv_sh(0, t - 48, sh);   ctr = &g_shready[0]; }
            else if (t < 96)  { conv_w(1, t - 64, W);     ctr = &g_wready[1]; }
            else if (t < 112) { conv_sh(1, t - 96, sh);   ctr = &g_shready[1]; }
            else if (t < 144) { conv_w(2, t - 112, W);    ctr = &g_wready[2]; }
            else if (t < 160) { conv_sh(2, t - 144, sh);  ctr = &g_shready[2]; }
            else if (t < 192) { conv_w(3, t - 160, W);    ctr = &g_wready[3]; }
            else              { conv_sh(3, t - 192, sh);  ctr = &g_shready[3]; }
            __threadfence();
            __syncthreads();
            if (tid == 0) atomicAdd(ctr, 1);
            continue;
        }

        const int tt = t - NCONV;
        const int layer = tt >> 10;
        const int mb = (tt >> 5) & 31;
        const int nb = tt & 31;

        if (tid == 0) {
            wait_ge(&g_wready[layer], 32);
            wait_ge(&g_shready[layer], 16);
            if (layer == 0) wait_ge(&g_xready, 16);
            else            wait_ge(&g_ready[layer - 1][mb], 32);
        }
        __syncthreads();

        process_tile(layer, mb * 128, nb * 128, smem,
                     bias_all, sc_all, out_h, out_c, out_final);

        __threadfence();
        __syncthreads();
        if (tid == 0) atomicAdd(&g_ready[layer][mb], 1);
    }
}

// ---------------- launch ----------------
extern "C" void kernel_launch(void* const* d_in, const int* in_sizes, int n_in,
                              void* d_out, int out_size) {
    const float* x  = (const float*)d_in[0];
    const float* sh = (const float*)d_in[1];
    const float* sc = (const float*)d_in[2];
    const float* W  = (const float*)d_in[3];
    const float* b  = (const float*)d_in[4];
    float* out = (float*)d_out;

    const size_t BH = (size_t)B_ * H_;
    float* out_final = out;
    float* out_h     = out + BH;
    float* out_c     = out + BH + DEPTH * BH;

    cudaFuncSetAttribute(lstm_all, cudaFuncAttributeMaxDynamicSharedMemorySize, SMEM_G);

    init_counters<<<1, 256>>>();
    lstm_all<<<GRID_P, 256, SMEM_G>>>(x, sh, W, b, sc, out_h, out_c, out_final);
}

// round 12
// speedup vs baseline: 1.0215x; 1.0215x over previous
#include <cuda_runtime.h>
#include <cuda_fp16.h>
#include <cstdint>

#define DEPTH 4
#define B_    4096
#define H_    1024
#define K_    2048
#define N4H   4096

// ---------------- device scratch ----------------
__device__ __half g_A[DEPTH][B_][K_];    // [prev_out | s_h] fp16
__device__ __half g_W[DEPTH][K_][N4H];   // gate-interleaved: col 4j+g = orig g*1024+j
__device__ int    g_ticket;
__device__ int    g_ready[DEPTH][32];    // finished n-tiles per (layer, m-block)

// ---------------- helpers ----------------
__device__ __forceinline__ uint32_t smem_u32(const void* p) {
    uint32_t a;
    asm("{ .reg .u64 t; cvta.to.shared.u64 t, %1; cvt.u32.u64 %0, t; }" : "=r"(a) : "l"(p));
    return a;
}
__device__ __forceinline__ void cp16(uint32_t dst, const void* src) {
    asm volatile("cp.async.cg.shared.global [%0], [%1], 16;"
                 :: "r"(dst), "l"(__cvta_generic_to_global(src)));
}
__device__ __forceinline__ void ldsm4(uint32_t* r, uint32_t addr) {
    asm volatile("ldmatrix.sync.aligned.m8n8.x4.shared.b16 {%0,%1,%2,%3}, [%4];"
                 : "=r"(r[0]), "=r"(r[1]), "=r"(r[2]), "=r"(r[3]) : "r"(addr));
}
__device__ __forceinline__ void ldsm4t(uint32_t* r, uint32_t addr) {
    asm volatile("ldmatrix.sync.aligned.m8n8.x4.trans.shared.b16 {%0,%1,%2,%3}, [%4];"
                 : "=r"(r[0]), "=r"(r[1]), "=r"(r[2]), "=r"(r[3]) : "r"(addr));
}
__device__ __forceinline__ void mma16816(float* c, const uint32_t* a, const uint32_t* b) {
    asm volatile("mma.sync.aligned.m16n8k16.row.col.f32.f16.f16.f32 "
                 "{%0,%1,%2,%3}, {%4,%5,%6,%7}, {%8,%9}, {%0,%1,%2,%3};"
                 : "+f"(c[0]), "+f"(c[1]), "+f"(c[2]), "+f"(c[3])
                 : "r"(a[0]), "r"(a[1]), "r"(a[2]), "r"(a[3]), "r"(b[0]), "r"(b[1]));
}
__device__ __forceinline__ float sigm(float x) { return 1.0f / (1.0f + __expf(-x)); }

__device__ __forceinline__ void wait_ge(const int* cp, int thr) {
    int v;
    for (;;) {
        asm volatile("ld.global.acquire.gpu.b32 %0, [%1];" : "=r"(v) : "l"(cp) : "memory");
        if (v >= thr) break;
        __nanosleep(128);
    }
}
__device__ __forceinline__ int peek(const int* cp) {
    int v;
    asm volatile("ld.global.acquire.gpu.b32 %0, [%1];" : "=r"(v) : "l"(cp) : "memory");
    return v;
}

// ---------------- prologue kernels (R9-proven: high-occupancy standalone) ----------------
__global__ void init_counters() {
    int t = threadIdx.x;
    if (t == 0) g_ticket = 0;
    if (t < DEPTH * 32) ((int*)g_ready)[t] = 0;
}
// W'[l][k][4j+g] = W[l][k][g*1024+j], fp16  (mapping verified: rel_err identical)
__global__ void cvt_w(const float* __restrict__ W) {
    size_t i = (size_t)blockIdx.x * blockDim.x + threadIdx.x;
    size_t l = i >> 21;
    size_t rem = i & ((1u << 21) - 1);
    size_t k = rem >> 10, j = rem & 1023;
    const float* src = W + (l * K_ + k) * N4H;
    float vi = src[j], vf = src[1024 + j], vo = src[2048 + j], vg = src[3072 + j];
    __half2* dst = (__half2*)&g_W[l][k][4 * j];
    dst[0] = __floats2half2_rn(vi, vf);
    dst[1] = __floats2half2_rn(vo, vg);
}
__global__ void pack_sh(const float* __restrict__ sh) {
    size_t i = (size_t)blockIdx.x * blockDim.x + threadIdx.x;
    size_t e = i * 4;
    size_t l = e / ((size_t)B_ * H_);
    size_t r = e % ((size_t)B_ * H_);
    size_t m = r >> 10, j = r & 1023;
    float4 v = ((const float4*)sh)[i];
    __half2* dst = (__half2*)&g_A[l][m][H_ + j];
    dst[0] = __floats2half2_rn(v.x, v.y);
    dst[1] = __floats2half2_rn(v.z, v.w);
}
__global__ void pack_x(const float* __restrict__ x) {
    size_t i = (size_t)blockIdx.x * blockDim.x + threadIdx.x;
    size_t e = i * 4;
    size_t m = e >> 10, j = e & 1023;
    float4 v = ((const float4*)x)[i];
    __half2* dst = (__half2*)&g_A[0][m][j];
    dst[0] = __floats2half2_rn(v.x, v.y);
    dst[1] = __floats2half2_rn(v.z, v.w);
}

// ---------------- tile config ----------------
#define BK      32
#define ASTRIDE 80
#define BSTRIDE 272
#define A_STG   (128 * ASTRIDE)    // 10240
#define B_STG   (BK * BSTRIDE)     // 8704
#define STG     (A_STG + B_STG)    // 18944
#define NSTAGE  5
#define CIN_STRIDE 144
#define CIN_BYTES  (128 * CIN_STRIDE)
#define SMEM_G  (NSTAGE * STG + CIN_BYTES)     // 113152
#define NTILES  (DEPTH * 32 * 32)              // 4096
#define GRID_P  296

__device__ __forceinline__ void load_stage_f(
    uint32_t sbase, const __half* Ag, const __half* Wg, int m0, int n0,
    int ar, int ac, int br, int bc, int s, int k0)
{
    uint32_t da = sbase + s * STG;
    uint32_t db = da + A_STG;
    cp16(da + ar * ASTRIDE + ac * 16,       Ag + (size_t)(m0 + ar) * K_ + k0 + ac * 8);
    cp16(da + ar * ASTRIDE + (ac + 1) * 16, Ag + (size_t)(m0 + ar) * K_ + k0 + (ac + 1) * 8);
    cp16(db + br * BSTRIDE + bc * 16,        Wg + (size_t)(k0 + br) * N4H + n0 + bc * 8);
    cp16(db + (br + 16) * BSTRIDE + bc * 16, Wg + (size_t)(k0 + br + 16) * N4H + n0 + bc * 8);
    asm volatile("cp.async.commit_group;" ::: "memory");
}

// ---------------- persistent fused GEMM + LSTM with cross-tile prefetch ----------------
__global__ void __launch_bounds__(256, 2)
lstm_all(const float* __restrict__ bias_all, const float* __restrict__ sc_all,
         float* __restrict__ out_h, float* __restrict__ out_c,
         float* __restrict__ out_final) {
    extern __shared__ __align__(16) char smem[];
    __shared__ int s_t, s_ok;
    const int tid = threadIdx.x;
    const int wid = tid >> 5, lane = tid & 31;
    const int wm = (wid >> 2) * 64, wn = (wid & 3) * 32;
    const uint32_t sbase = smem_u32(smem);
    const uint32_t scin  = sbase + NSTAGE * STG;

    const int ar = tid >> 1, ac = (tid & 1) * 2;
    const int br = tid >> 4, bc = tid & 15;

    // tile-invariant fragment offsets
    uint32_t aoff[4], boff[2];
    #pragma unroll
    for (int mf = 0; mf < 4; ++mf)
        aoff[mf] = (wm + mf * 16 + (lane & 15)) * ASTRIDE + (lane >> 4) * 16;
    #pragma unroll
    for (int ns = 0; ns < 2; ++ns)
        boff[ns] = (lane & 15) * BSTRIDE + (wn + ns * 16 + (lane >> 4) * 8) * 2;

    if (tid == 0) s_t = atomicAdd(&g_ticket, 1);
    __syncthreads();
    int cur = s_t;
    bool pf = false;

    while (cur < NTILES) {
        const int layer = cur >> 10;
        const int mb = (cur >> 5) & 31;
        const int nb = cur & 31;
        const int m0 = mb * 128, n0 = nb * 128;
        const int jbase = n0 >> 2;

        const float* bias = bias_all + (size_t)layer * N4H;
        const float* c_in = sc_all + (size_t)layer * B_ * H_;
        float* h_out = out_h + (size_t)layer * B_ * H_;
        float* c_out = out_c + (size_t)layer * B_ * H_;
        float* final_out = (layer == DEPTH - 1) ? out_final : nullptr;
        const __half* Ag = &g_A[layer][0][0];
        const __half* Wg = &g_W[layer][0][0];
        __half* a_next = (layer + 1 < DEPTH) ? &g_A[layer + 1][0][0] : nullptr;

        if (!pf) {
            if (tid == 0 && layer > 0) wait_ge(&g_ready[layer - 1][mb], 32);
            __syncthreads();
        }

        float acc[4][4][4];
        #pragma unroll
        for (int i = 0; i < 4; ++i)
            #pragma unroll
            for (int j = 0; j < 4; ++j)
                #pragma unroll
                for (int q2 = 0; q2 < 4; ++q2) acc[i][j][q2] = 0.f;

        // c_in prefetch (one group)
        #pragma unroll
        for (int it = 0; it < 4; ++it) {
            int idx = tid + 256 * it;
            int r = idx >> 3, ch = idx & 7;
            cp16(scin + r * CIN_STRIDE + ch * 16,
                 c_in + (size_t)(m0 + r) * H_ + jbase + ch * 4);
        }
        asm volatile("cp.async.commit_group;" ::: "memory");

        if (!pf) {
            load_stage_f(sbase, Ag, Wg, m0, n0, ar, ac, br, bc, 0, 0);
            load_stage_f(sbase, Ag, Wg, m0, n0, ar, ac, br, bc, 1, BK);
            load_stage_f(sbase, Ag, Wg, m0, n0, ar, ac, br, bc, 2, 2 * BK);
        }

        auto subiter = [&](int st, int pf_k0, bool do_pf) {
            const uint32_t da = sbase + st * STG;
            const uint32_t db = da + A_STG;
            uint32_t af[4][4], bf[2][4];
            #pragma unroll
            for (int mf = 0; mf < 4; ++mf) ldsm4(af[mf], da + aoff[mf]);
            #pragma unroll
            for (int ns = 0; ns < 2; ++ns) ldsm4t(bf[ns], db + boff[ns]);
            if (do_pf)
                load_stage_f(sbase, Ag, Wg, m0, n0, ar, ac, br, bc,
                             (pf_k0 / BK) % NSTAGE, pf_k0);
            #pragma unroll
            for (int mf = 0; mf < 4; ++mf)
                #pragma unroll
                for (int nf = 0; nf < 4; ++nf)
                    mma16816(acc[mf][nf], af[mf], &bf[nf >> 1][(nf & 1) * 2]);
            #pragma unroll
            for (int mf = 0; mf < 4; ++mf) ldsm4(af[mf], da + aoff[mf] + 32);
            #pragma unroll
            for (int ns = 0; ns < 2; ++ns) ldsm4t(bf[ns], db + boff[ns] + 16 * BSTRIDE);
            #pragma unroll
            for (int mf = 0; mf < 4; ++mf)
                #pragma unroll
                for (int nf = 0; nf < 4; ++nf)
                    mma16816(acc[mf][nf], af[mf], &bf[nf >> 1][(nf & 1) * 2]);
        };

        const int NIT = K_ / BK;  // 64
        #pragma unroll 1
        for (int kt = 0; kt < NIT; kt += 2) {
            if (kt + 2 < NIT) asm volatile("cp.async.wait_group 1;" ::: "memory");
            else              asm volatile("cp.async.wait_group 0;" ::: "memory");
            __syncthreads();
            subiter(kt % NSTAGE,       (kt + 3) * BK, kt + 3 < NIT);
            subiter((kt + 1) % NSTAGE, (kt + 4) * BK, kt + 4 < NIT);
        }
        __syncthreads();

        // ---- grab next ticket; opportunistic prefetch of its stages 0-2 ----
        if (tid == 0) s_t = atomicAdd(&g_ticket, 1);
        __syncthreads();
        const int nxt = s_t;
        bool pfn = false;
        if (nxt < NTILES) {
            const int lN = nxt >> 10, mbN = (nxt >> 5) & 31;
            if (tid == 0)
                s_ok = (lN == 0) || (peek(&g_ready[lN - 1][mbN]) >= 32);
            __syncthreads();
            if (s_ok) {
                const int m0N = ((nxt >> 5) & 31) * 128, n0N = (nxt & 31) * 128;
                const __half* AgN = &g_A[lN][0][0];
                const __half* WgN = &g_W[lN][0][0];
                load_stage_f(sbase, AgN, WgN, m0N, n0N, ar, ac, br, bc, 0, 0);
                load_stage_f(sbase, AgN, WgN, m0N, n0N, ar, ac, br, bc, 1, BK);
                load_stage_f(sbase, AgN, WgN, m0N, n0N, ar, ac, br, bc, 2, 2 * BK);
                pfn = true;
            }
        }

        // ---- LSTM epilogue (staging in slot-3/4 region; mapping verified) ----
        float* sh_h = (float*)(smem + 3 * STG);          // [128][33] = 16896 B
        float* sh_c = sh_h + 128 * 33;                   // [128][33]
        const float* sh_cin = (const float*)(smem + NSTAGE * STG);

        const int q = lane & 3;
        const bool has_if = (q & 1) == 0;
        const int rloc = wm + (lane >> 2);

        float bi[4], bfs[4], bo[4], bg[4];
        int jloc[4];
        #pragma unroll
        for (int nf = 0; nf < 4; ++nf) {
            int jl = (wn >> 2) + nf * 2 + (q >> 1);
            jloc[nf] = jl;
            int j = jbase + jl;
            bi[nf]  = bias[j];
            bfs[nf] = bias[1024 + j];
            bo[nf]  = bias[2048 + j];
            bg[nf]  = bias[3072 + j];
        }

        #pragma unroll
        for (int mf = 0; mf < 4; ++mf) {
            #pragma unroll
            for (int nf = 0; nf < 4; ++nf) {
                float v0 = acc[mf][nf][0], v1 = acc[mf][nf][1];
                float v2 = acc[mf][nf][2], v3 = acc[mf][nf][3];
                float p0 = __shfl_xor_sync(0xffffffffu, v0, 1);
                float p1 = __shfl_xor_sync(0xffffffffu, v1, 1);
                float p2 = __shfl_xor_sync(0xffffffffu, v2, 1);
                float p3 = __shfl_xor_sync(0xffffffffu, v3, 1);
                float zi, zf, zo, zg;
                int ml;
                if (has_if) { zi = v0; zf = v1; zo = p0; zg = p1; ml = rloc + mf * 16; }
                else        { zi = p2; zf = p3; zo = v2; zg = v3; ml = rloc + mf * 16 + 8; }
                const int jl = jloc[nf];
                float ig = sigm(zi + bi[nf]);
                float fg = sigm(zf + bfs[nf]);
                float og = sigm(zo + bo[nf]);
                float gg = tanhf(zg + bg[nf]);
                float cn = sh_cin[ml * 36 + jl] * fg + gg * ig;
                float hn = tanhf(cn) * og;
                sh_h[ml * 33 + jl] = hn;
                sh_c[ml * 33 + jl] = cn;
            }
        }
        __syncthreads();

        // ---- coalesced output pass ----
        #pragma unroll
        for (int it = 0; it < 16; ++it) {
            int idx = tid + 256 * it;
            int r = idx >> 5, c2 = idx & 31;
            float hv = sh_h[r * 33 + c2];
            float cv = sh_c[r * 33 + c2];
            const size_t off = (size_t)(m0 + r) * H_ + jbase + c2;
            h_out[off] = hv;
            c_out[off] = cv;
            if (final_out) final_out[off] = hv;
            if (a_next) a_next[(size_t)(m0 + r) * K_ + jbase + c2] = __float2half(hv);
        }
        __threadfence();
        __syncthreads();
        if (tid == 0) atomicAdd(&g_ready[layer][mb], 1);

        cur = nxt;
        pf = pfn;
    }
}

// ---------------- launch ----------------
extern "C" void kernel_launch(void* const* d_in, const int* in_sizes, int n_in,
                              void* d_out, int out_size) {
    const float* x  = (const float*)d_in[0];
    const float* sh = (const float*)d_in[1];
    const float* sc = (const float*)d_in[2];
    const float* W  = (const float*)d_in[3];
    const float* b  = (const float*)d_in[4];
    float* out = (float*)d_out;

    const size_t BH = (size_t)B_ * H_;
    float* out_final = out;
    float* out_h     = out + BH;
    float* out_c     = out + BH + DEPTH * BH;

    cudaFuncSetAttribute(lstm_all, cudaFuncAttributeMaxDynamicSharedMemorySize, SMEM_G);

    init_counters<<<1, 256>>>();
    cvt_w<<<(DEPTH * (size_t)K_ * 1024) / 256, 256>>>(W);
    pack_sh<<<(DEPTH * BH / 4) / 256, 256>>>(sh);
    pack_x<<<(BH / 4) / 256, 256>>>(x);

    lstm_all<<<GRID_P, 256, SMEM_G>>>(b, sc, out_h, out_c, out_final);
}

// round 13
// speedup vs baseline: 1.0671x; 1.0446x over previous
#include <cuda_runtime.h>
#include <cuda_fp16.h>
#include <cstdint>

#define DEPTH 4
#define B_    4096
#define H_    1024
#define K_    2048
#define N4H   4096

// ---------------- device scratch ----------------
__device__ __half g_A[DEPTH][B_][K_];    // [prev_out | s_h] fp16
__device__ __half g_W[DEPTH][K_][N4H];   // gate-interleaved: col 4j+g = orig g*1024+j
__device__ int    g_ticket;
__device__ int    g_ready[DEPTH][32];    // finished n-tiles per (layer, m-block)

// ---------------- helpers ----------------
__device__ __forceinline__ uint32_t smem_u32(const void* p) {
    uint32_t a;
    asm("{ .reg .u64 t; cvta.to.shared.u64 t, %1; cvt.u32.u64 %0, t; }" : "=r"(a) : "l"(p));
    return a;
}
__device__ __forceinline__ void cp16(uint32_t dst, const void* src) {
    asm volatile("cp.async.cg.shared.global [%0], [%1], 16;"
                 :: "r"(dst), "l"(__cvta_generic_to_global(src)));
}
__device__ __forceinline__ void ldsm4(uint32_t* r, uint32_t addr) {
    asm volatile("ldmatrix.sync.aligned.m8n8.x4.shared.b16 {%0,%1,%2,%3}, [%4];"
                 : "=r"(r[0]), "=r"(r[1]), "=r"(r[2]), "=r"(r[3]) : "r"(addr));
}
__device__ __forceinline__ void ldsm4t(uint32_t* r, uint32_t addr) {
    asm volatile("ldmatrix.sync.aligned.m8n8.x4.trans.shared.b16 {%0,%1,%2,%3}, [%4];"
                 : "=r"(r[0]), "=r"(r[1]), "=r"(r[2]), "=r"(r[3]) : "r"(addr));
}
__device__ __forceinline__ void mma16816(float* c, const uint32_t* a, const uint32_t* b) {
    asm volatile("mma.sync.aligned.m16n8k16.row.col.f32.f16.f16.f32 "
                 "{%0,%1,%2,%3}, {%4,%5,%6,%7}, {%8,%9}, {%0,%1,%2,%3};"
                 : "+f"(c[0]), "+f"(c[1]), "+f"(c[2]), "+f"(c[3])
                 : "r"(a[0]), "r"(a[1]), "r"(a[2]), "r"(a[3]), "r"(b[0]), "r"(b[1]));
}
__device__ __forceinline__ float sigm(float x) { return 1.0f / (1.0f + __expf(-x)); }

__device__ __forceinline__ void wait_ge(const int* cp, int thr) {
    int v;
    for (;;) {
        asm volatile("ld.global.acquire.gpu.b32 %0, [%1];" : "=r"(v) : "l"(cp) : "memory");
        if (v >= thr) break;
        __nanosleep(128);
    }
}

// ---------------- merged prologue: init + cvt_w + pack_x + pack_sh ----------------
// blocks [0,4096): W gate-interleave (2048 j-quads each)
// blocks [4096,4608): x pack (2048 float4 each)
// blocks [4608,6656): s_h pack (2048 float4 each)
#define PREP_WBLK 4096
#define PREP_XBLK 512
#define PREP_SBLK 2048
#define PREP_GRID (PREP_WBLK + PREP_XBLK + PREP_SBLK)

__global__ void __launch_bounds__(256)
prep(const float* __restrict__ W, const float* __restrict__ x,
     const float* __restrict__ sh) {
    const int b = blockIdx.x;
    const int tid = threadIdx.x;
    if (b == 0) {
        if (tid == 0) g_ticket = 0;
        if (tid < DEPTH * 32) ((int*)g_ready)[tid] = 0;
    }
    if (b < PREP_WBLK) {
        // W'[l][k][4j+g] = W[l][k][g*1024+j] (mapping verified: rel_err identical)
        #pragma unroll
        for (int it = 0; it < 8; ++it) {
            size_t i = (size_t)b * 2048 + it * 256 + tid;   // (l,k,j)
            size_t l = i >> 21;
            size_t rem = i & ((1u << 21) - 1);
            size_t k = rem >> 10, j = rem & 1023;
            const float* src = W + (l * K_ + k) * N4H;
            float vi = src[j], vf = src[1024 + j], vo = src[2048 + j], vg = src[3072 + j];
            __half2* dst = (__half2*)&g_W[l][k][4 * j];
            dst[0] = __floats2half2_rn(vi, vf);
            dst[1] = __floats2half2_rn(vo, vg);
        }
    } else if (b < PREP_WBLK + PREP_XBLK) {
        #pragma unroll
        for (int it = 0; it < 8; ++it) {
            size_t i = (size_t)(b - PREP_WBLK) * 2048 + it * 256 + tid;  // float4 idx
            size_t e = i * 4;
            size_t m = e >> 10, j = e & 1023;
            float4 v = ((const float4*)x)[i];
            __half2* dst = (__half2*)&g_A[0][m][j];
            dst[0] = __floats2half2_rn(v.x, v.y);
            dst[1] = __floats2half2_rn(v.z, v.w);
        }
    } else {
        #pragma unroll
        for (int it = 0; it < 8; ++it) {
            size_t i = (size_t)(b - PREP_WBLK - PREP_XBLK) * 2048 + it * 256 + tid;
            size_t e = i * 4;
            size_t l = e / ((size_t)B_ * H_);
            size_t r = e % ((size_t)B_ * H_);
            size_t m = r >> 10, j = r & 1023;
            float4 v = ((const float4*)sh)[i];
            __half2* dst = (__half2*)&g_A[l][m][H_ + j];
            dst[0] = __floats2half2_rn(v.x, v.y);
            dst[1] = __floats2half2_rn(v.z, v.w);
        }
    }
}

// ---------------- tile config ----------------
#define BK      32
#define ASTRIDE 80
#define BSTRIDE 272
#define A_STG   (128 * ASTRIDE)    // 10240
#define B_STG   (BK * BSTRIDE)     // 8704
#define STG     (A_STG + B_STG)    // 18944
#define NSTAGE  5
#define CIN_STRIDE 144
#define CIN_BYTES  (128 * CIN_STRIDE)
#define SMEM_G  (NSTAGE * STG + CIN_BYTES)     // 113152
#define NTILES  (DEPTH * 32 * 32)              // 4096
#define GRID_P  296

// ---------------- persistent fused GEMM + LSTM (R9-proven loop) ----------------
__global__ void __launch_bounds__(256, 2)
lstm_all(const float* __restrict__ bias_all, const float* __restrict__ sc_all,
         float* __restrict__ out_h, float* __restrict__ out_c,
         float* __restrict__ out_final) {
    extern __shared__ __align__(16) char smem[];
    __shared__ int s_t;
    const int tid = threadIdx.x;
    const int wid = tid >> 5, lane = tid & 31;
    const int wm = (wid >> 2) * 64, wn = (wid & 3) * 32;
    const uint32_t sbase = smem_u32(smem);
    const uint32_t scin  = sbase + NSTAGE * STG;

    const int ar = tid >> 1, ac = (tid & 1) * 2;
    const int br = tid >> 4, bc = tid & 15;

    uint32_t aoff[4], boff[2];
    #pragma unroll
    for (int mf = 0; mf < 4; ++mf)
        aoff[mf] = (wm + mf * 16 + (lane & 15)) * ASTRIDE + (lane >> 4) * 16;
    #pragma unroll
    for (int ns = 0; ns < 2; ++ns)
        boff[ns] = (lane & 15) * BSTRIDE + (wn + ns * 16 + (lane >> 4) * 8) * 2;

    for (;;) {
        if (tid == 0) s_t = atomicAdd(&g_ticket, 1);
        __syncthreads();
        const int t = s_t;
        if (t >= NTILES) return;
        const int layer = t >> 10;
        const int mb = (t >> 5) & 31;
        const int nb = t & 31;
        const int m0 = mb * 128, n0 = nb * 128;
        const int jbase = n0 >> 2;

        const float* bias = bias_all + (size_t)layer * N4H;
        const float* c_in = sc_all + (size_t)layer * B_ * H_;
        float* h_out = out_h + (size_t)layer * B_ * H_;
        float* c_out = out_c + (size_t)layer * B_ * H_;
        float* final_out = (layer == DEPTH - 1) ? out_final : nullptr;
        const __half* Ag = &g_A[layer][0][0];
        const __half* Wg = &g_W[layer][0][0];
        __half* a_next = (layer + 1 < DEPTH) ? &g_A[layer + 1][0][0] : nullptr;

        if (layer > 0) {
            if (tid == 0) wait_ge(&g_ready[layer - 1][mb], 32);
            __syncthreads();
        }

        auto load_stage = [&](int s, int k0) {
            uint32_t da = sbase + s * STG;
            uint32_t db = da + A_STG;
            cp16(da + ar * ASTRIDE + ac * 16,       Ag + (size_t)(m0 + ar) * K_ + k0 + ac * 8);
            cp16(da + ar * ASTRIDE + (ac + 1) * 16, Ag + (size_t)(m0 + ar) * K_ + k0 + (ac + 1) * 8);
            cp16(db + br * BSTRIDE + bc * 16,        Wg + (size_t)(k0 + br) * N4H + n0 + bc * 8);
            cp16(db + (br + 16) * BSTRIDE + bc * 16, Wg + (size_t)(k0 + br + 16) * N4H + n0 + bc * 8);
            asm volatile("cp.async.commit_group;" ::: "memory");
        };

        float acc[4][4][4];
        #pragma unroll
        for (int i = 0; i < 4; ++i)
            #pragma unroll
            for (int j = 0; j < 4; ++j)
                #pragma unroll
                for (int q2 = 0; q2 < 4; ++q2) acc[i][j][q2] = 0.f;

        // c_in prefetch (oldest group)
        #pragma unroll
        for (int it = 0; it < 4; ++it) {
            int idx = tid + 256 * it;
            int r = idx >> 3, ch = idx & 7;
            cp16(scin + r * CIN_STRIDE + ch * 16,
                 c_in + (size_t)(m0 + r) * H_ + jbase + ch * 4);
        }
        asm volatile("cp.async.commit_group;" ::: "memory");

        load_stage(0, 0);
        load_stage(1, BK);
        load_stage(2, 2 * BK);

        auto subiter = [&](int st, int pf_slot, int pf_k0, bool do_pf) {
            const uint32_t da = sbase + st * STG;
            const uint32_t db = da + A_STG;
            uint32_t af[4][4], bf[2][4];
            #pragma unroll
            for (int mf = 0; mf < 4; ++mf) ldsm4(af[mf], da + aoff[mf]);
            #pragma unroll
            for (int ns = 0; ns < 2; ++ns) ldsm4t(bf[ns], db + boff[ns]);
            if (do_pf) load_stage(pf_slot, pf_k0);
            #pragma unroll
            for (int mf = 0; mf < 4; ++mf)
                #pragma unroll
                for (int nf = 0; nf < 4; ++nf)
                    mma16816(acc[mf][nf], af[mf], &bf[nf >> 1][(nf & 1) * 2]);
            #pragma unroll
            for (int mf = 0; mf < 4; ++mf) ldsm4(af[mf], da + aoff[mf] + 32);
            #pragma unroll
            for (int ns = 0; ns < 2; ++ns) ldsm4t(bf[ns], db + boff[ns] + 16 * BSTRIDE);
            #pragma unroll
            for (int mf = 0; mf < 4; ++mf)
                #pragma unroll
                for (int nf = 0; nf < 4; ++nf)
                    mma16816(acc[mf][nf], af[mf], &bf[nf >> 1][(nf & 1) * 2]);
        };

        const int NIT = K_ / BK;  // 64
        #pragma unroll 1
        for (int kt = 0; kt < NIT; kt += 2) {
            if (kt + 2 < NIT) asm volatile("cp.async.wait_group 1;" ::: "memory");
            else              asm volatile("cp.async.wait_group 0;" ::: "memory");
            __syncthreads();
            subiter(kt % NSTAGE,       (kt + 3) % NSTAGE, (kt + 3) * BK, kt + 3 < NIT);
            subiter((kt + 1) % NSTAGE, (kt + 4) % NSTAGE, (kt + 4) * BK, kt + 4 < NIT);
        }
        __syncthreads();

        // ---- LSTM epilogue (staging in slot-3/4 region; mapping verified) ----
        float* sh_h = (float*)(smem + 3 * STG);          // [128][33]
        float* sh_c = sh_h + 128 * 33;                   // [128][33]
        const float* sh_cin = (const float*)(smem + NSTAGE * STG);

        const int q = lane & 3;
        const bool has_if = (q & 1) == 0;
        const int rloc = wm + (lane >> 2);

        float bi[4], bfs[4], bo[4], bg[4];
        int jloc[4];
        #pragma unroll
        for (int nf = 0; nf < 4; ++nf) {
            int jl = (wn >> 2) + nf * 2 + (q >> 1);
            jloc[nf] = jl;
            int j = jbase + jl;
            bi[nf]  = bias[j];
            bfs[nf] = bias[1024 + j];
            bo[nf]  = bias[2048 + j];
            bg[nf]  = bias[3072 + j];
        }

        #pragma unroll
        for (int mf = 0; mf < 4; ++mf) {
            #pragma unroll
            for (int nf = 0; nf < 4; ++nf) {
                float v0 = acc[mf][nf][0], v1 = acc[mf][nf][1];
                float v2 = acc[mf][nf][2], v3 = acc[mf][nf][3];
                float p0 = __shfl_xor_sync(0xffffffffu, v0, 1);
                float p1 = __shfl_xor_sync(0xffffffffu, v1, 1);
                float p2 = __shfl_xor_sync(0xffffffffu, v2, 1);
                float p3 = __shfl_xor_sync(0xffffffffu, v3, 1);
                float zi, zf, zo, zg;
                int ml;
                if (has_if) { zi = v0; zf = v1; zo = p0; zg = p1; ml = rloc + mf * 16; }
                else        { zi = p2; zf = p3; zo = v2; zg = v3; ml = rloc + mf * 16 + 8; }
                const int jl = jloc[nf];
                float ig = sigm(zi + bi[nf]);
                float fg = sigm(zf + bfs[nf]);
                float og = sigm(zo + bo[nf]);
                float gg = tanhf(zg + bg[nf]);
                float cn = sh_cin[ml * 36 + jl] * fg + gg * ig;
                float hn = tanhf(cn) * og;
                sh_h[ml * 33 + jl] = hn;
                sh_c[ml * 33 + jl] = cn;
            }
        }
        __syncthreads();

        // ---- coalesced output pass ----
        #pragma unroll
        for (int it = 0; it < 16; ++it) {
            int idx = tid + 256 * it;
            int r = idx >> 5, c2 = idx & 31;
            float hv = sh_h[r * 33 + c2];
            float cv = sh_c[r * 33 + c2];
            const size_t off = (size_t)(m0 + r) * H_ + jbase + c2;
            h_out[off] = hv;
            c_out[off] = cv;
            if (final_out) final_out[off] = hv;
            if (a_next) a_next[(size_t)(m0 + r) * K_ + jbase + c2] = __float2half(hv);
        }
        __threadfence();
        __syncthreads();
        if (tid == 0) atomicAdd(&g_ready[layer][mb], 1);
    }
}

// ---------------- launch ----------------
extern "C" void kernel_launch(void* const* d_in, const int* in_sizes, int n_in,
                              void* d_out, int out_size) {
    const float* x  = (const float*)d_in[0];
    const float* sh = (const float*)d_in[1];
    const float* sc = (const float*)d_in[2];
    const float* W  = (const float*)d_in[3];
    const float* b  = (const float*)d_in[4];
    float* out = (float*)d_out;

    const size_t BH = (size_t)B_ * H_;
    float* out_final = out;
    float* out_h     = out + BH;
    float* out_c     = out + BH + DEPTH * BH;

    cudaFuncSetAttribute(lstm_all, cudaFuncAttributeMaxDynamicSharedMemorySize, SMEM_G);

    prep<<<PREP_GRID, 256>>>(W, x, sh);
    lstm_all<<<GRID_P, 256, SMEM_G>>>(b, sc, out_h, out_c, out_final);
}

// round 14
// speedup vs baseline: 1.0732x; 1.0058x over previous
#include <cuda_runtime.h>
#include <cuda_fp16.h>
#include <cstdint>

#define DEPTH 4
#define B_    4096
#define H_    1024
#define K_    2048
#define N4H   4096

// ---------------- device scratch ----------------
__device__ __half g_A[DEPTH][B_][K_];    // [prev_out | s_h] fp16
__device__ __half g_W[DEPTH][K_][N4H];   // gate-interleaved: col 4j+g = orig g*1024+j
__device__ int    g_ticket;
__device__ int    g_ready[DEPTH][32];    // finished n-tiles per (layer, m-block)

// ---------------- helpers ----------------
__device__ __forceinline__ uint32_t smem_u32(const void* p) {
    uint32_t a;
    asm("{ .reg .u64 t; cvta.to.shared.u64 t, %1; cvt.u32.u64 %0, t; }" : "=r"(a) : "l"(p));
    return a;
}
__device__ __forceinline__ void cp16(uint32_t dst, const void* src) {
    asm volatile("cp.async.cg.shared.global [%0], [%1], 16;"
                 :: "r"(dst), "l"(__cvta_generic_to_global(src)));
}
__device__ __forceinline__ void ldsm4(uint32_t* r, uint32_t addr) {
    asm volatile("ldmatrix.sync.aligned.m8n8.x4.shared.b16 {%0,%1,%2,%3}, [%4];"
                 : "=r"(r[0]), "=r"(r[1]), "=r"(r[2]), "=r"(r[3]) : "r"(addr));
}
__device__ __forceinline__ void ldsm4t(uint32_t* r, uint32_t addr) {
    asm volatile("ldmatrix.sync.aligned.m8n8.x4.trans.shared.b16 {%0,%1,%2,%3}, [%4];"
                 : "=r"(r[0]), "=r"(r[1]), "=r"(r[2]), "=r"(r[3]) : "r"(addr));
}
__device__ __forceinline__ void mma16816(float* c, const uint32_t* a, const uint32_t* b) {
    asm volatile("mma.sync.aligned.m16n8k16.row.col.f32.f16.f16.f32 "
                 "{%0,%1,%2,%3}, {%4,%5,%6,%7}, {%8,%9}, {%0,%1,%2,%3};"
                 : "+f"(c[0]), "+f"(c[1]), "+f"(c[2]), "+f"(c[3])
                 : "r"(a[0]), "r"(a[1]), "r"(a[2]), "r"(a[3]), "r"(b[0]), "r"(b[1]));
}
__device__ __forceinline__ float sigm(float x) { return 1.0f / (1.0f + __expf(-x)); }

__device__ __forceinline__ void wait_ge(const int* cp, int thr) {
    int v;
    for (;;) {
        asm volatile("ld.global.acquire.gpu.b32 %0, [%1];" : "=r"(v) : "l"(cp) : "memory");
        if (v >= thr) break;
        __nanosleep(128);
    }
}
__device__ __forceinline__ void stcs4(float* p, float4 v) {
    asm volatile("st.global.cs.v4.f32 [%0], {%1,%2,%3,%4};"
                 :: "l"(__cvta_generic_to_global(p)), "f"(v.x), "f"(v.y), "f"(v.z), "f"(v.w)
                 : "memory");
}

// ---------------- merged prologue (R12-proven) ----------------
#define PREP_WBLK 4096
#define PREP_XBLK 512
#define PREP_SBLK 2048
#define PREP_GRID (PREP_WBLK + PREP_XBLK + PREP_SBLK)

__global__ void __launch_bounds__(256)
prep(const float* __restrict__ W, const float* __restrict__ x,
     const float* __restrict__ sh) {
    const int b = blockIdx.x;
    const int tid = threadIdx.x;
    if (b == 0) {
        if (tid == 0) g_ticket = 0;
        if (tid < DEPTH * 32) ((int*)g_ready)[tid] = 0;
    }
    if (b < PREP_WBLK) {
        #pragma unroll
        for (int it = 0; it < 8; ++it) {
            size_t i = (size_t)b * 2048 + it * 256 + tid;
            size_t l = i >> 21;
            size_t rem = i & ((1u << 21) - 1);
            size_t k = rem >> 10, j = rem & 1023;
            const float* src = W + (l * K_ + k) * N4H;
            float vi = src[j], vf = src[1024 + j], vo = src[2048 + j], vg = src[3072 + j];
            __half2* dst = (__half2*)&g_W[l][k][4 * j];
            dst[0] = __floats2half2_rn(vi, vf);
            dst[1] = __floats2half2_rn(vo, vg);
        }
    } else if (b < PREP_WBLK + PREP_XBLK) {
        #pragma unroll
        for (int it = 0; it < 8; ++it) {
            size_t i = (size_t)(b - PREP_WBLK) * 2048 + it * 256 + tid;
            size_t e = i * 4;
            size_t m = e >> 10, j = e & 1023;
            float4 v = ((const float4*)x)[i];
            __half2* dst = (__half2*)&g_A[0][m][j];
            dst[0] = __floats2half2_rn(v.x, v.y);
            dst[1] = __floats2half2_rn(v.z, v.w);
        }
    } else {
        #pragma unroll
        for (int it = 0; it < 8; ++it) {
            size_t i = (size_t)(b - PREP_WBLK - PREP_XBLK) * 2048 + it * 256 + tid;
            size_t e = i * 4;
            size_t l = e / ((size_t)B_ * H_);
            size_t r = e % ((size_t)B_ * H_);
            size_t m = r >> 10, j = r & 1023;
            float4 v = ((const float4*)sh)[i];
            __half2* dst = (__half2*)&g_A[l][m][H_ + j];
            dst[0] = __floats2half2_rn(v.x, v.y);
            dst[1] = __floats2half2_rn(v.z, v.w);
        }
    }
}

// ---------------- tile config ----------------
#define BK      32
#define ASTRIDE 80
#define BSTRIDE 272
#define A_STG   (128 * ASTRIDE)    // 10240
#define B_STG   (BK * BSTRIDE)     // 8704
#define STG     (A_STG + B_STG)    // 18944
#define NSTAGE  5
#define CIN_STRIDE 144
#define CIN_BYTES  (128 * CIN_STRIDE)
#define SMEM_G  (NSTAGE * STG + CIN_BYTES)     // 113152
#define NTILES  (DEPTH * 32 * 32)              // 4096
#define GRID_P  296

// ---------------- persistent fused GEMM + LSTM (R9-proven loop) ----------------
__global__ void __launch_bounds__(256, 2)
lstm_all(const float* __restrict__ bias_all, const float* __restrict__ sc_all,
         float* __restrict__ out_h, float* __restrict__ out_c,
         float* __restrict__ out_final) {
    extern __shared__ __align__(16) char smem[];
    __shared__ int s_t;
    const int tid = threadIdx.x;
    const int wid = tid >> 5, lane = tid & 31;
    const int wm = (wid >> 2) * 64, wn = (wid & 3) * 32;
    const uint32_t sbase = smem_u32(smem);
    const uint32_t scin  = sbase + NSTAGE * STG;

    const int ar = tid >> 1, ac = (tid & 1) * 2;
    const int br = tid >> 4, bc = tid & 15;

    uint32_t aoff[4], boff[2];
    #pragma unroll
    for (int mf = 0; mf < 4; ++mf)
        aoff[mf] = (wm + mf * 16 + (lane & 15)) * ASTRIDE + (lane >> 4) * 16;
    #pragma unroll
    for (int ns = 0; ns < 2; ++ns)
        boff[ns] = (lane & 15) * BSTRIDE + (wn + ns * 16 + (lane >> 4) * 8) * 2;

    for (;;) {
        if (tid == 0) s_t = atomicAdd(&g_ticket, 1);
        __syncthreads();
        const int t = s_t;
        if (t >= NTILES) return;
        const int layer = t >> 10;
        const int mb = (t >> 5) & 31;
        const int nb = t & 31;
        const int m0 = mb * 128, n0 = nb * 128;
        const int jbase = n0 >> 2;

        const float* bias = bias_all + (size_t)layer * N4H;
        const float* c_in = sc_all + (size_t)layer * B_ * H_;
        float* h_out = out_h + (size_t)layer * B_ * H_;
        float* c_out = out_c + (size_t)layer * B_ * H_;
        float* final_out = (layer == DEPTH - 1) ? out_final : nullptr;
        const __half* Ag = &g_A[layer][0][0];
        const __half* Wg = &g_W[layer][0][0];
        __half* a_next = (layer + 1 < DEPTH) ? &g_A[layer + 1][0][0] : nullptr;

        if (layer > 0) {
            if (tid == 0) wait_ge(&g_ready[layer - 1][mb], 32);
            __syncthreads();
        }

        auto load_stage = [&](int s, int k0) {
            uint32_t da = sbase + s * STG;
            uint32_t db = da + A_STG;
            cp16(da + ar * ASTRIDE + ac * 16,       Ag + (size_t)(m0 + ar) * K_ + k0 + ac * 8);
            cp16(da + ar * ASTRIDE + (ac + 1) * 16, Ag + (size_t)(m0 + ar) * K_ + k0 + (ac + 1) * 8);
            cp16(db + br * BSTRIDE + bc * 16,        Wg + (size_t)(k0 + br) * N4H + n0 + bc * 8);
            cp16(db + (br + 16) * BSTRIDE + bc * 16, Wg + (size_t)(k0 + br + 16) * N4H + n0 + bc * 8);
            asm volatile("cp.async.commit_group;" ::: "memory");
        };

        float acc[4][4][4];
        #pragma unroll
        for (int i = 0; i < 4; ++i)
            #pragma unroll
            for (int j = 0; j < 4; ++j)
                #pragma unroll
                for (int q2 = 0; q2 < 4; ++q2) acc[i][j][q2] = 0.f;

        // c_in prefetch (oldest group)
        #pragma unroll
        for (int it = 0; it < 4; ++it) {
            int idx = tid + 256 * it;
            int r = idx >> 3, ch = idx & 7;
            cp16(scin + r * CIN_STRIDE + ch * 16,
                 c_in + (size_t)(m0 + r) * H_ + jbase + ch * 4);
        }
        asm volatile("cp.async.commit_group;" ::: "memory");

        load_stage(0, 0);
        load_stage(1, BK);
        load_stage(2, 2 * BK);

        auto subiter = [&](int st, int pf_slot, int pf_k0, bool do_pf) {
            const uint32_t da = sbase + st * STG;
            const uint32_t db = da + A_STG;
            uint32_t af[4][4], bf[2][4];
            #pragma unroll
            for (int mf = 0; mf < 4; ++mf) ldsm4(af[mf], da + aoff[mf]);
            #pragma unroll
            for (int ns = 0; ns < 2; ++ns) ldsm4t(bf[ns], db + boff[ns]);
            if (do_pf) load_stage(pf_slot, pf_k0);
            #pragma unroll
            for (int mf = 0; mf < 4; ++mf)
                #pragma unroll
                for (int nf = 0; nf < 4; ++nf)
                    mma16816(acc[mf][nf], af[mf], &bf[nf >> 1][(nf & 1) * 2]);
            #pragma unroll
            for (int mf = 0; mf < 4; ++mf) ldsm4(af[mf], da + aoff[mf] + 32);
            #pragma unroll
            for (int ns = 0; ns < 2; ++ns) ldsm4t(bf[ns], db + boff[ns] + 16 * BSTRIDE);
            #pragma unroll
            for (int mf = 0; mf < 4; ++mf)
                #pragma unroll
                for (int nf = 0; nf < 4; ++nf)
                    mma16816(acc[mf][nf], af[mf], &bf[nf >> 1][(nf & 1) * 2]);
        };

        const int NIT = K_ / BK;  // 64
        #pragma unroll 1
        for (int kt = 0; kt < NIT; kt += 2) {
            if (kt + 2 < NIT) asm volatile("cp.async.wait_group 1;" ::: "memory");
            else              asm volatile("cp.async.wait_group 0;" ::: "memory");
            __syncthreads();
            subiter(kt % NSTAGE,       (kt + 3) % NSTAGE, (kt + 3) * BK, kt + 3 < NIT);
            subiter((kt + 1) % NSTAGE, (kt + 4) % NSTAGE, (kt + 4) * BK, kt + 4 < NIT);
        }
        __syncthreads();

        // ---- LSTM epilogue (staging in slot-3/4 region; mapping verified) ----
        float* sh_h = (float*)(smem + 3 * STG);          // [128][33]
        float* sh_c = sh_h + 128 * 33;                   // [128][33]
        const float* sh_cin = (const float*)(smem + NSTAGE * STG);

        const int q = lane & 3;
        const bool has_if = (q & 1) == 0;
        const int rloc = wm + (lane >> 2);

        float bi[4], bfs[4], bo[4], bg[4];
        int jloc[4];
        #pragma unroll
        for (int nf = 0; nf < 4; ++nf) {
            int jl = (wn >> 2) + nf * 2 + (q >> 1);
            jloc[nf] = jl;
            int j = jbase + jl;
            bi[nf]  = bias[j];
            bfs[nf] = bias[1024 + j];
            bo[nf]  = bias[2048 + j];
            bg[nf]  = bias[3072 + j];
        }

        #pragma unroll
        for (int mf = 0; mf < 4; ++mf) {
            #pragma unroll
            for (int nf = 0; nf < 4; ++nf) {
                float v0 = acc[mf][nf][0], v1 = acc[mf][nf][1];
                float v2 = acc[mf][nf][2], v3 = acc[mf][nf][3];
                float p0 = __shfl_xor_sync(0xffffffffu, v0, 1);
                float p1 = __shfl_xor_sync(0xffffffffu, v1, 1);
                float p2 = __shfl_xor_sync(0xffffffffu, v2, 1);
                float p3 = __shfl_xor_sync(0xffffffffu, v3, 1);
                float zi, zf, zo, zg;
                int ml;
                if (has_if) { zi = v0; zf = v1; zo = p0; zg = p1; ml = rloc + mf * 16; }
                else        { zi = p2; zf = p3; zo = v2; zg = v3; ml = rloc + mf * 16 + 8; }
                const int jl = jloc[nf];
                float ig = sigm(zi + bi[nf]);
                float fg = sigm(zf + bfs[nf]);
                float og = sigm(zo + bo[nf]);
                float gg = tanhf(zg + bg[nf]);
                float cn = sh_cin[ml * 36 + jl] * fg + gg * ig;
                float hn = tanhf(cn) * og;
                sh_h[ml * 33 + jl] = hn;
                sh_c[ml * 33 + jl] = cn;
            }
        }
        __syncthreads();

        // ---- vectorized output pass: 128 rows x 8 float4-chunks = 1024 units ----
        #pragma unroll
        for (int it = 0; it < 4; ++it) {
            int idx = tid + 256 * it;            // 0..1023
            int r = idx >> 3, c4 = (idx & 7) * 4;
            float4 hv = make_float4(sh_h[r * 33 + c4],     sh_h[r * 33 + c4 + 1],
                                    sh_h[r * 33 + c4 + 2], sh_h[r * 33 + c4 + 3]);
            float4 cv = make_float4(sh_c[r * 33 + c4],     sh_c[r * 33 + c4 + 1],
                                    sh_c[r * 33 + c4 + 2], sh_c[r * 33 + c4 + 3]);
            const size_t off = (size_t)(m0 + r) * H_ + jbase + c4;
            stcs4(&h_out[off], hv);
            stcs4(&c_out[off], cv);
            if (final_out) stcs4(&final_out[off], hv);
            if (a_next) {
                __half2 pk[2];
                pk[0] = __floats2half2_rn(hv.x, hv.y);
                pk[1] = __floats2half2_rn(hv.z, hv.w);
                *(uint2*)&a_next[(size_t)(m0 + r) * K_ + jbase + c4] = *(uint2*)pk;
            }
        }
        __syncthreads();
        // release-ordered publish (replaces __threadfence + relaxed atomic)
        if (tid == 0)
            asm volatile("red.release.gpu.global.add.s32 [%0], 1;"
                         :: "l"(__cvta_generic_to_global(&g_ready[layer][mb])) : "memory");
    }
}

// ---------------- launch ----------------
extern "C" void kernel_launch(void* const* d_in, const int* in_sizes, int n_in,
                              void* d_out, int out_size) {
    const float* x  = (const float*)d_in[0];
    const float* sh = (const float*)d_in[1];
    const float* sc = (const float*)d_in[2];
    const float* W  = (const float*)d_in[3];
    const float* b  = (const float*)d_in[4];
    float* out = (float*)d_out;

    const size_t BH = (size_t)B_ * H_;
    float* out_final = out;
    float* out_h     = out + BH;
    float* out_c     = out + BH + DEPTH * BH;

    cudaFuncSetAttribute(lstm_all, cudaFuncAttributeMaxDynamicSharedMemorySize, SMEM_G);

    prep<<<PREP_GRID, 256>>>(W, x, sh);
    lstm_all<<<GRID_P, 256, SMEM_G>>>(b, sc, out_h, out_c, out_final);
}